// round 9
// baseline (speedup 1.0000x reference)
#include <cuda_runtime.h>
#include <cuda_fp16.h>
#include <stdint.h>
#include <math.h>

// Problem dims (fixed by the dataset)
#define BB    8
#define HWP   256
#define NPIX  (8*512*256)     // 1,048,576
#define KDIM  4608            // 512 cin * 9 taps
#define MROWS 2048            // 4 gates * 512 cout

// ---------------- device scratch (no allocations allowed) ----------------
__device__ float g_m[HWP * 256];
__device__ float g_myA[BB * HWP];
__device__ float g_CW[4][NPIX];        // conv(AM,Wg)+bg (timestep-invariant)
__device__ float g_G[4][NPIX];         // per-ts gate pre-activations
__device__ float g_h[NPIX];
__device__ float g_c[NPIX];
// fp16 weights, K reordered as k = tap*512 + cin. Set 0 = W gates, set 1 = U gates.
__device__ __align__(16) __half g_Wh[2][MROWS * KDIM];
// transposed fp16 image of current conv input: Xt[b][hw][cin]
__device__ __align__(16) __half g_Xt[2048 * 512];

// ---------------- helpers ----------------
__device__ __forceinline__ uint32_t smem_u32(const void* p) {
    uint32_t a;
    asm("{ .reg .u64 t; cvta.to.shared.u64 t, %1; cvt.u32.u64 %0, t; }" : "=r"(a) : "l"(p));
    return a;
}
__device__ __forceinline__ void cp16(uint32_t smaddr, const void* gaddr) {
    asm volatile("cp.async.cg.shared.global [%0], [%1], 16;" :: "r"(smaddr), "l"(gaddr));
}
__device__ __forceinline__ void cp16z(uint32_t smaddr, const void* gaddr, uint32_t srcsz) {
    asm volatile("cp.async.cg.shared.global [%0], [%1], 16, %2;"
                 :: "r"(smaddr), "l"(gaddr), "r"(srcsz));
}
__device__ __forceinline__ void cp_commit() {
    asm volatile("cp.async.commit_group;" ::: "memory");
}
__device__ __forceinline__ void cp_wait1() {
    asm volatile("cp.async.wait_group 1;" ::: "memory");
}
__device__ __forceinline__ void ldsm4(uint32_t* r, uint32_t addr) {
    asm volatile("ldmatrix.sync.aligned.m8n8.x4.shared.b16 {%0,%1,%2,%3}, [%4];"
                 : "=r"(r[0]), "=r"(r[1]), "=r"(r[2]), "=r"(r[3]) : "r"(addr));
}
__device__ __forceinline__ void mma16816(float* c, const uint32_t* A, const uint32_t* B) {
    asm volatile(
        "mma.sync.aligned.m16n8k16.row.col.f32.f16.f16.f32 "
        "{%0,%1,%2,%3}, {%4,%5,%6,%7}, {%8,%9}, {%0,%1,%2,%3};"
        : "+f"(c[0]), "+f"(c[1]), "+f"(c[2]), "+f"(c[3])
        : "r"(A[0]), "r"(A[1]), "r"(A[2]), "r"(A[3]), "r"(B[0]), "r"(B[1]));
}

// ---------------- attention precompute ----------------
__global__ void k_m(const float* __restrict__ WQ, const float* __restrict__ WK) {
    int hw = blockIdx.x, t = threadIdx.x;
    const float* base = WQ + ((size_t)hw * 512) * 256 + t;
    float s = 0.f;
#pragma unroll 4
    for (int e = 0; e < 512; e++) s += WK[e] * base[(size_t)e * 256];
    g_m[hw * 256 + t] = s;
}

__global__ void k_att(const float* __restrict__ txt, const float* __restrict__ WV,
                      const float* __restrict__ Wsw, const float* __restrict__ Wsb) {
    int b = blockIdx.x, hw = threadIdx.x;
    __shared__ float st[256];
    __shared__ float sc[256];
    st[hw] = txt[b * 256 + hw];
    __syncthreads();
    float s = 0.f;
#pragma unroll 4
    for (int t = 0; t < 256; t++) s += st[t] * g_m[hw * 256 + t];
    s /= sqrtf(512.0f);
    sc[hw] = s;
    __syncthreads();
    int w = hw & 15;
    float mx = -1e30f;
#pragma unroll
    for (int h2 = 0; h2 < 16; h2++) mx = fmaxf(mx, sc[h2 * 16 + w]);
    float den = 0.f;
#pragma unroll
    for (int h2 = 0; h2 < 16; h2++) den += expf(sc[h2 * 16 + w] - mx);
    float attn = expf(s - mx) / den;
    float vw = 0.f;
    for (int e = 0; e < 512; e++) vw += WV[e] * Wsw[e];
    g_myA[b * 256 + hw] = 1.f + attn * vw + Wsb[0];
}

// ---------------- weight convert + K-reorder (fp16) ----------------
struct WPtrs { const float* p[8]; };  // Wi,Wf,Wc,Wo, Ui,Uf,Uc,Uo

__global__ void k_wsplit(WPtrs wp) {
    __shared__ float srow[KDIM];
    int bid = blockIdx.x;           // 0..4095
    int s = bid >> 11;              // set (0=W, 1=U)
    int m = bid & 2047;             // stacked row: g*512+cout
    const float* src = wp.p[s * 4 + (m >> 9)] + (size_t)(m & 511) * KDIM;
    for (int i = threadIdx.x; i < KDIM; i += 256) srow[i] = src[i];
    __syncthreads();
    __half* dh = g_Wh[s] + (size_t)m * KDIM;
    for (int k = threadIdx.x; k < KDIM; k += 256) {
        int tap = k >> 9, cin = k & 511;
        dh[k] = __float2half_rn(srow[cin * 9 + tap]);
    }
}

// ---------------- prep: transpose [b][cin][hw] -> Xt[b][hw][cin] fp16 ----------------
__global__ void k_prep(const float* __restrict__ In, int scaled) {
    __shared__ float T[64][65];
    int hwT = blockIdx.x;     // 0..3
    int cinT = blockIdx.y;    // 0..7
    int b = blockIdx.z;       // 0..7
    int tid = threadIdx.x;
#pragma unroll
    for (int i = 0; i < 16; i++) {
        int idx = i * 256 + tid;
        int ci = idx >> 6, hw = idx & 63;
        T[ci][hw] = In[((size_t)(b * 512 + cinT * 64 + ci)) * 256 + hwT * 64 + hw];
    }
    __syncthreads();
#pragma unroll
    for (int i = 0; i < 16; i++) {
        int idx = i * 256 + tid;
        int hw = idx >> 6, ci = idx & 63;
        float v = T[ci][hw];
        if (scaled) v *= g_myA[b * 256 + hwT * 64 + hw];
        g_Xt[((size_t)(b * 256 + hwT * 64 + hw)) * 512 + cinT * 64 + ci] = __float2half_rn(v);
    }
}

// ---------------- HMMA GEMM, implicit im2col with B-halo tap reuse ----------------
// CTA tile: M=128 (weights rows), N=256 (one whole image). 8 warps, warp 64x64.
// K loop: 8 cin-subchunks x 9 taps (chunk = 64 K-values).
// B: per sub, halo tile [18 rows][16 cols][64 cin] loaded ONCE, all 9 taps served
//    from smem via per-lane ldmatrix row gather (invalid cols -> zero row).
struct GArgs {
    const __half* Aw;       // fp16 weights, [2048][KDIM], K = tap*512+cin
    const float* bias[4];
    const float* base;      // optional additive (g_CW), nullable
    float* out;
};

#define A_ST 16384                  // one A stage: 128 rows * 128B
#define B_ST 36864                  // one B stage: 288 px * 128B
#define BOFF (3 * A_ST)             // 49152
#define ZOFF (BOFF + 2 * B_ST)      // 122880 : 128B zero row
#define GEMM_SMEM (ZOFF + 128)      // 123008

__global__ __launch_bounds__(256, 1) void k_gemm(GArgs a) {
    extern __shared__ __align__(128) char sm[];
    uint32_t usm = smem_u32(sm);
    int tid = threadIdx.x, wid = tid >> 5, lane = tid & 31;
    int mt = blockIdx.x;   // 0..15  (M tile)
    int nt = blockIdx.y;   // 0..7   (image / batch)

    const __half* Aw = a.Aw + (size_t)mt * 128 * KDIM;
    const __half* Xb = g_Xt + (size_t)nt * 256 * 512;

    int m0 = (wid >> 2) * 64;
    int n0 = (wid & 3) * 64;

    float acc[4][8][4];
#pragma unroll
    for (int mf = 0; mf < 4; mf++)
#pragma unroll
        for (int nf = 0; nf < 8; nf++)
#pragma unroll
            for (int q = 0; q < 4; q++) acc[mf][nf][q] = 0.f;

    // zero row for invalid-column lanes
    if (tid < 32) ((float*)(sm + ZOFF))[tid] = 0.f;

    // ---- A loader: 4 (row,seg) slots per thread ----
    int segq = tid & 7;
    int row0 = tid >> 3;           // 0..31
    uint32_t aDst[4];
    const __half* aSrc[4];
#pragma unroll
    for (int i = 0; i < 4; i++) {
        int row = row0 + i * 32;
        aDst[i] = (uint32_t)(row * 128 + ((segq ^ (row & 7)) << 4));
        aSrc[i] = Aw + (size_t)row * KDIM + segq * 8;
    }
    auto load_A = [&](int j, int st) {   // chunk j -> stage st
        int sub = j / 9, tap = j - sub * 9;
        int koff = tap * 512 + sub * 64;
        uint32_t sA = usm + st * A_ST;
#pragma unroll
        for (int i = 0; i < 4; i++) cp16(sA + aDst[i], aSrc[i] + koff);
    };

    // B loader: rows rlo..rhi-1 of halo (18 rows, r' = rowh-1) for cin-sub `sub` -> stage st
    auto load_B = [&](int sub, int st, int rlo, int rhi) {
        uint32_t sB = usm + BOFF + st * B_ST;
        int nops = (rhi - rlo) * 128;
        for (int op = tid; op < nops; op += 256) {
            int rowh = rlo + (op >> 7);
            int rem = op & 127;
            int c = rem >> 3, seg = rem & 7;
            int rp = rowh - 1;               // -1..16
            int idx = rowh * 16 + c;
            uint32_t dst = sB + idx * 128 + ((seg ^ (idx & 7)) << 4);
            bool ok = (unsigned)rp < 16u;
            const __half* src = Xb + ((size_t)(ok ? (rp * 16 + c) : 0)) * 512 + sub * 64 + seg * 8;
            cp16z(dst, src, ok ? 16u : 0u);
        }
    };

    // prologue: group0 = B(sub0) full + A(chunk0); group1 = A(chunk1)
    load_B(0, 0, 0, 18);
    load_A(0, 0);
    cp_commit();
    load_A(1, 1);
    cp_commit();

    // ldmatrix lane pieces
    int laneA = lane & 15, cA = lane >> 4;
    int laneB = ((lane >> 4) << 3) + (lane & 7), cB = (lane >> 3) & 1;
    // B slice schedule over 8 taps: rows [rs[t], rs[t+1])
    const int rs[9] = {0, 3, 6, 8, 10, 12, 14, 16, 18};

    for (int j = 0; j < 72; j++) {
        int sub = j / 9, tap = j - sub * 9;
        cp_wait1();
        __syncthreads();
        // issue next loads (A two ahead; B slices of next sub during taps 0..7)
        if (j + 2 < 72) load_A(j + 2, (j + 2) % 3);
        if (sub < 7 && tap < 8) load_B(sub + 1, (sub + 1) & 1, rs[tap], rs[tap + 1]);
        cp_commit();

        uint32_t sA = usm + (j % 3) * A_ST;
        uint32_t sB = usm + BOFF + (sub & 1) * B_ST;
        int dr = (tap >= 6) ? 2 : ((tap >= 3) ? 1 : 0);
        int dc = tap - dr * 3;

        // per-warp B row gather addresses for this tap (4 groups of 16 pixels)
        uint32_t bBase[4];
        uint32_t bS7[4];
#pragma unroll
        for (int g4 = 0; g4 < 4; g4++) {
            int hw = n0 + g4 * 16 + laneB;
            int r = hw >> 4, c = hw & 15;
            int rp = r + dr - 1;             // -1..16 (always stored in halo)
            int cp = c + dc - 1;
            bool ok = (unsigned)cp < 16u;
            int idx = (rp + 1) * 16 + cp;
            bBase[g4] = ok ? (sB + idx * 128) : (usm + ZOFF);
            bS7[g4] = ok ? (uint32_t)(idx & 7) : 0u;
        }

#pragma unroll
        for (int ks = 0; ks < 4; ks++) {
            uint32_t Af[4][4], Bf[8][2];
#pragma unroll
            for (int mf = 0; mf < 4; mf++) {
                int rowL = m0 + mf * 16 + laneA;
                int cu = 2 * ks + cA;
                ldsm4(Af[mf], sA + (uint32_t)(rowL << 7) + (uint32_t)((cu ^ (rowL & 7)) << 4));
            }
#pragma unroll
            for (int g4 = 0; g4 < 4; g4++) {
                int cu = 2 * ks + cB;
                uint32_t t[4];
                ldsm4(t, bBase[g4] + ((cu ^ bS7[g4]) << 4));
                Bf[2 * g4][0] = t[0]; Bf[2 * g4][1] = t[1];
                Bf[2 * g4 + 1][0] = t[2]; Bf[2 * g4 + 1][1] = t[3];
            }
#pragma unroll
            for (int mf = 0; mf < 4; mf++)
#pragma unroll
                for (int nf = 0; nf < 8; nf++) mma16816(acc[mf][nf], Af[mf], Bf[nf]);
        }
    }

    // epilogue: bias + optional base add, float2 stores
    const float* basep = a.base;
    int b = nt;
#pragma unroll
    for (int mf = 0; mf < 4; mf++) {
        int mg = mt * 128 + m0 + mf * 16 + (lane >> 2);
        int g = mg >> 9, cout = mg & 511;
        float bv0 = a.bias[g][cout];
        float bv1 = a.bias[g][cout + 8];
        size_t ob = (size_t)g * NPIX + ((size_t)b * 512 + cout) * 256;
#pragma unroll
        for (int nf = 0; nf < 8; nf++) {
            int hw = n0 + nf * 8 + ((lane & 3) << 1);
            size_t i0 = ob + hw;
            size_t i1 = i0 + 8 * 256;
            float2 v0 = make_float2(acc[mf][nf][0] + bv0, acc[mf][nf][1] + bv0);
            float2 v1 = make_float2(acc[mf][nf][2] + bv1, acc[mf][nf][3] + bv1);
            if (basep) {
                float2 t0 = *(const float2*)(basep + i0);
                float2 t1 = *(const float2*)(basep + i1);
                v0.x += t0.x; v0.y += t0.y;
                v1.x += t1.x; v1.y += t1.y;
            }
            *(float2*)(a.out + i0) = v0;
            *(float2*)(a.out + i1) = v1;
        }
    }
}

// ---------------- LSTM elementwise update ----------------
__global__ void k_update(const float* __restrict__ cprev, float* __restrict__ cnew,
                         float* __restrict__ hnew) {
    int idx = blockIdx.x * 256 + threadIdx.x;
    float gi = g_G[0][idx], gf = g_G[1][idx], gc = g_G[2][idx], go = g_G[3][idx];
    float i = 1.f / (1.f + expf(-gi));
    float f = 1.f / (1.f + expf(-gf));
    float g = tanhf(gc);
    float o = 1.f / (1.f + expf(-go));
    float c = g * i + f * cprev[idx];
    cnew[idx] = c;
    hnew[idx] = tanhf(c) * o;
}

// ---------------- launch ----------------
extern "C" void kernel_launch(void* const* d_in, const int* in_sizes, int n_in,
                              void* d_out, int out_size) {
    const float* x    = (const float*)d_in[0];
    const float* txt  = (const float*)d_in[1];
    // d_in[2..6] dead (softmax over size-1 axis == 1)
    const float* Wi_w = (const float*)d_in[7];
    const float* Wi_b = (const float*)d_in[8];
    const float* Ui_w = (const float*)d_in[9];
    const float* Ui_b = (const float*)d_in[10];
    const float* Wf_w = (const float*)d_in[11];
    const float* Wf_b = (const float*)d_in[12];
    const float* Uf_w = (const float*)d_in[13];
    const float* Uf_b = (const float*)d_in[14];
    const float* Wc_w = (const float*)d_in[15];
    const float* Wc_b = (const float*)d_in[16];
    const float* Uc_w = (const float*)d_in[17];
    const float* Uc_b = (const float*)d_in[18];
    const float* Wo_w = (const float*)d_in[19];
    const float* Wo_b = (const float*)d_in[20];
    const float* Uo_w = (const float*)d_in[21];
    const float* Uo_b = (const float*)d_in[22];
    const float* WQ   = (const float*)d_in[23];
    const float* WK   = (const float*)d_in[24];
    const float* WV   = (const float*)d_in[25];
    const float* Wsw  = (const float*)d_in[26];
    const float* Wsb  = (const float*)d_in[27];
    float* out = (float*)d_out;

    float *pCW, *pG, *pH, *pC;
    __half *pWh;
    cudaGetSymbolAddress((void**)&pCW, g_CW);
    cudaGetSymbolAddress((void**)&pG,  g_G);
    cudaGetSymbolAddress((void**)&pH,  g_h);
    cudaGetSymbolAddress((void**)&pC,  g_c);
    cudaGetSymbolAddress((void**)&pWh, g_Wh);

    cudaFuncSetAttribute(k_gemm, cudaFuncAttributeMaxDynamicSharedMemorySize, GEMM_SMEM);

    WPtrs wp;
    wp.p[0] = Wi_w; wp.p[1] = Wf_w; wp.p[2] = Wc_w; wp.p[3] = Wo_w;
    wp.p[4] = Ui_w; wp.p[5] = Uf_w; wp.p[6] = Uc_w; wp.p[7] = Uo_w;
    k_wsplit<<<4096, 256>>>(wp);

    k_m<<<256, 256>>>(WQ, WK);
    k_att<<<8, 256>>>(txt, WV, Wsw, Wsb);

    // precompute conv(AM, Wg) + bg once (AM = myA*x applied inside prep)
    k_prep<<<dim3(4, 8, 8), 256>>>(x, 1);
    {
        GArgs ga;
        ga.Aw = pWh;                         // W gates
        ga.bias[0] = Wi_b; ga.bias[1] = Wf_b; ga.bias[2] = Wc_b; ga.bias[3] = Wo_b;
        ga.base = nullptr;
        ga.out = pCW;
        k_gemm<<<dim3(16, 8), 256, GEMM_SMEM>>>(ga);
    }

    // 4-timestep recurrence: conv(h, Ug) + CW per step
    for (int ts = 0; ts < 4; ts++) {
        k_prep<<<dim3(4, 8, 8), 256>>>((ts == 0) ? x : pH, 0);
        GArgs gu;
        gu.Aw = pWh + (size_t)MROWS * KDIM;   // U gates
        gu.bias[0] = Ui_b; gu.bias[1] = Uf_b; gu.bias[2] = Uc_b; gu.bias[3] = Uo_b;
        gu.base = pCW;
        gu.out = pG;
        k_gemm<<<dim3(16, 8), 256, GEMM_SMEM>>>(gu);
        k_update<<<NPIX / 256, 256>>>((ts == 0) ? x : pC, pC,
                                      (ts == 3) ? out : pH);
    }
}

// round 12
// speedup vs baseline: 1.0089x; 1.0089x over previous
#include <cuda_runtime.h>
#include <cuda_fp16.h>
#include <stdint.h>
#include <math.h>

// Problem dims (fixed by the dataset)
#define BB    8
#define HWP   256
#define NPIX  (8*512*256)     // 1,048,576
#define KDIM  4608            // 512 cin * 9 taps
#define MROWS 2048            // 4 gates * 512 cout  (m = cout*4 + gate)

// ---------------- device scratch (no allocations allowed) ----------------
__device__ float g_m[HWP * 256];
__device__ float g_myA[BB * HWP];
__device__ float g_CW[MROWS * 2048];   // conv(AM,Wg)+bg as matrix [m][n], n = b*256+hw
__device__ float g_c[NPIX];
// fp16 weights, K = tap*512 + cin, rows m = cout*4+gate. Set 0 = W gates, 1 = U gates.
__device__ __align__(16) __half g_Wh[2][MROWS * KDIM];
// transposed fp16 image of current conv input: Xt[b][hw][cin]
__device__ __align__(16) __half g_Xt[2048 * 512];

// ---------------- helpers ----------------
__device__ __forceinline__ uint32_t smem_u32(const void* p) {
    uint32_t a;
    asm("{ .reg .u64 t; cvta.to.shared.u64 t, %1; cvt.u32.u64 %0, t; }" : "=r"(a) : "l"(p));
    return a;
}
__device__ __forceinline__ void cp16(uint32_t smaddr, const void* gaddr) {
    asm volatile("cp.async.cg.shared.global [%0], [%1], 16;" :: "r"(smaddr), "l"(gaddr));
}
__device__ __forceinline__ void cp16z(uint32_t smaddr, const void* gaddr, uint32_t srcsz) {
    asm volatile("cp.async.cg.shared.global [%0], [%1], 16, %2;"
                 :: "r"(smaddr), "l"(gaddr), "r"(srcsz));
}
__device__ __forceinline__ void cp_commit() {
    asm volatile("cp.async.commit_group;" ::: "memory");
}
__device__ __forceinline__ void cp_wait1() {
    asm volatile("cp.async.wait_group 1;" ::: "memory");
}
__device__ __forceinline__ void ldsm4(uint32_t* r, uint32_t addr) {
    asm volatile("ldmatrix.sync.aligned.m8n8.x4.shared.b16 {%0,%1,%2,%3}, [%4];"
                 : "=r"(r[0]), "=r"(r[1]), "=r"(r[2]), "=r"(r[3]) : "r"(addr));
}
__device__ __forceinline__ void mma16816(float* c, const uint32_t* A, const uint32_t* B) {
    asm volatile(
        "mma.sync.aligned.m16n8k16.row.col.f32.f16.f16.f32 "
        "{%0,%1,%2,%3}, {%4,%5,%6,%7}, {%8,%9}, {%0,%1,%2,%3};"
        : "+f"(c[0]), "+f"(c[1]), "+f"(c[2]), "+f"(c[3])
        : "r"(A[0]), "r"(A[1]), "r"(A[2]), "r"(A[3]), "r"(B[0]), "r"(B[1]));
}

// ---------------- attention precompute ----------------
__global__ void k_m(const float* __restrict__ WQ, const float* __restrict__ WK) {
    int hw = blockIdx.x, t = threadIdx.x;
    const float* base = WQ + ((size_t)hw * 512) * 256 + t;
    float s = 0.f;
#pragma unroll 4
    for (int e = 0; e < 512; e++) s += WK[e] * base[(size_t)e * 256];
    g_m[hw * 256 + t] = s;
}

__global__ void k_att(const float* __restrict__ txt, const float* __restrict__ WV,
                      const float* __restrict__ Wsw, const float* __restrict__ Wsb) {
    int b = blockIdx.x, hw = threadIdx.x;
    __shared__ float st[256];
    __shared__ float sc[256];
    st[hw] = txt[b * 256 + hw];
    __syncthreads();
    float s = 0.f;
#pragma unroll 4
    for (int t = 0; t < 256; t++) s += st[t] * g_m[hw * 256 + t];
    s /= sqrtf(512.0f);
    sc[hw] = s;
    __syncthreads();
    int w = hw & 15;
    float mx = -1e30f;
#pragma unroll
    for (int h2 = 0; h2 < 16; h2++) mx = fmaxf(mx, sc[h2 * 16 + w]);
    float den = 0.f;
#pragma unroll
    for (int h2 = 0; h2 < 16; h2++) den += expf(sc[h2 * 16 + w] - mx);
    float attn = expf(s - mx) / den;
    float vw = 0.f;
    for (int e = 0; e < 512; e++) vw += WV[e] * Wsw[e];
    g_myA[b * 256 + hw] = 1.f + attn * vw + Wsb[0];
}

// ---------------- weight convert + K-reorder (fp16), gate-inner M ----------------
struct WPtrs { const float* p[8]; };  // Wi,Wf,Wc,Wo, Ui,Uf,Uc,Uo

__global__ void k_wsplit(WPtrs wp) {
    __shared__ float srow[KDIM];
    int bid = blockIdx.x;           // 0..4095
    int s = bid >> 11;              // set (0=W, 1=U)
    int m = bid & 2047;             // row: cout*4 + gate
    const float* src = wp.p[s * 4 + (m & 3)] + (size_t)(m >> 2) * KDIM;
    for (int i = threadIdx.x; i < KDIM; i += 256) srow[i] = src[i];
    __syncthreads();
    __half* dh = g_Wh[s] + (size_t)m * KDIM;
    for (int k = threadIdx.x; k < KDIM; k += 256) {
        int tap = k >> 9, cin = k & 511;
        dh[k] = __float2half_rn(srow[cin * 9 + tap]);
    }
}

// ---------------- prep: transpose [b][cin][hw] -> Xt[b][hw][cin] fp16 ----------------
__global__ void k_prep(const float* __restrict__ In, int scaled) {
    __shared__ float T[64][65];
    int hwT = blockIdx.x;     // 0..3
    int cinT = blockIdx.y;    // 0..7
    int b = blockIdx.z;       // 0..7
    int tid = threadIdx.x;
#pragma unroll
    for (int i = 0; i < 16; i++) {
        int idx = i * 256 + tid;
        int ci = idx >> 6, hw = idx & 63;
        T[ci][hw] = In[((size_t)(b * 512 + cinT * 64 + ci)) * 256 + hwT * 64 + hw];
    }
    __syncthreads();
#pragma unroll
    for (int i = 0; i < 16; i++) {
        int idx = i * 256 + tid;
        int hw = idx >> 6, ci = idx & 63;
        float v = T[ci][hw];
        if (scaled) v *= g_myA[b * 256 + hwT * 64 + hw];
        g_Xt[((size_t)(b * 256 + hwT * 64 + hw)) * 512 + cinT * 64 + ci] = __float2half_rn(v);
    }
}

// ---------------- HMMA GEMM, implicit im2col + fused LSTM epilogue ----------------
// CTA tile: M=128 (= 32 couts x 4 gates), N=256 (one image). 8 warps, warp 64x64.
// mode 0: write CW matrix (+bias). mode 1: LSTM update, write c + Xt(fp16 h).
// mode 2: LSTM update, write c + out(fp32 h).
struct GArgs {
    const __half* Aw;
    const float* bias[4];
    float* cw;              // mode0: write target; mode1/2: base read
    const float* cprev;     // mode1/2
    float* cnew;            // mode1/2
    float* out;             // mode2
    int mode;
};

#define A_ST 16384                  // one A stage: 128 rows * 128B
#define B_ST 36864                  // one B stage: 288 px * 128B
#define BOFF (3 * A_ST)             // 49152
#define ZOFF (BOFF + 2 * B_ST)      // 122880 : 128B zero row
#define SPITCH 257
#define SMXT_OFF (128 * SPITCH * 4) // 131584
#define GEMM_SMEM (SMXT_OFF + 256 * 32 * 2)  // 147968

__global__ __launch_bounds__(256, 1) void k_gemm(GArgs a) {
    extern __shared__ __align__(128) char sm[];
    uint32_t usm = smem_u32(sm);
    int tid = threadIdx.x, wid = tid >> 5, lane = tid & 31;
    int mt = blockIdx.x;   // 0..15  (M tile)
    int nt = blockIdx.y;   // 0..7   (image / batch)

    const __half* Aw = a.Aw + (size_t)mt * 128 * KDIM;
    const __half* Xb = g_Xt + (size_t)nt * 256 * 512;

    int m0 = (wid >> 2) * 64;
    int n0 = (wid & 3) * 64;

    float acc[4][8][4];
#pragma unroll
    for (int mf = 0; mf < 4; mf++)
#pragma unroll
        for (int nf = 0; nf < 8; nf++)
#pragma unroll
            for (int q = 0; q < 4; q++) acc[mf][nf][q] = 0.f;

    // zero row for invalid-column lanes
    if (tid < 32) ((float*)(sm + ZOFF))[tid] = 0.f;

    // ---- A loader ----
    int segq = tid & 7;
    int row0 = tid >> 3;           // 0..31
    uint32_t aDst[4];
    const __half* aSrc[4];
#pragma unroll
    for (int i = 0; i < 4; i++) {
        int row = row0 + i * 32;
        aDst[i] = (uint32_t)(row * 128 + ((segq ^ (row & 7)) << 4));
        aSrc[i] = Aw + (size_t)row * KDIM + segq * 8;
    }
    auto load_A = [&](int j, int st) {
        int sub = j / 9, tap = j - sub * 9;
        int koff = tap * 512 + sub * 64;
        uint32_t sA = usm + st * A_ST;
#pragma unroll
        for (int i = 0; i < 4; i++) cp16(sA + aDst[i], aSrc[i] + koff);
    };

    auto load_B = [&](int sub, int st, int rlo, int rhi) {
        uint32_t sB = usm + BOFF + st * B_ST;
        int nops = (rhi - rlo) * 128;
        for (int op = tid; op < nops; op += 256) {
            int rowh = rlo + (op >> 7);
            int rem = op & 127;
            int c = rem >> 3, seg = rem & 7;
            int rp = rowh - 1;
            int idx = rowh * 16 + c;
            uint32_t dst = sB + idx * 128 + ((seg ^ (idx & 7)) << 4);
            bool ok = (unsigned)rp < 16u;
            const __half* src = Xb + ((size_t)(ok ? (rp * 16 + c) : 0)) * 512 + sub * 64 + seg * 8;
            cp16z(dst, src, ok ? 16u : 0u);
        }
    };

    load_B(0, 0, 0, 18);
    load_A(0, 0);
    cp_commit();
    load_A(1, 1);
    cp_commit();

    int laneA = lane & 15, cA = lane >> 4;
    int laneB = ((lane >> 4) << 3) + (lane & 7), cB = (lane >> 3) & 1;
    const int rs[9] = {0, 3, 6, 8, 10, 12, 14, 16, 18};

    for (int j = 0; j < 72; j++) {
        int sub = j / 9, tap = j - sub * 9;
        cp_wait1();
        __syncthreads();
        if (j + 2 < 72) load_A(j + 2, (j + 2) % 3);
        if (sub < 7 && tap < 8) load_B(sub + 1, (sub + 1) & 1, rs[tap], rs[tap + 1]);
        cp_commit();

        uint32_t sA = usm + (j % 3) * A_ST;
        uint32_t sB = usm + BOFF + (sub & 1) * B_ST;
        int dr = (tap >= 6) ? 2 : ((tap >= 3) ? 1 : 0);
        int dc = tap - dr * 3;

        uint32_t bBase[4];
        uint32_t bS7[4];
#pragma unroll
        for (int g4 = 0; g4 < 4; g4++) {
            int hw = n0 + g4 * 16 + laneB;
            int r = hw >> 4, c = hw & 15;
            int rp = r + dr - 1;
            int cp = c + dc - 1;
            bool ok = (unsigned)cp < 16u;
            int idx = (rp + 1) * 16 + cp;
            bBase[g4] = ok ? (sB + idx * 128) : (usm + ZOFF);
            bS7[g4] = ok ? (uint32_t)(idx & 7) : 0u;
        }

#pragma unroll
        for (int ks = 0; ks < 4; ks++) {
            uint32_t Af[4][4], Bf[8][2];
#pragma unroll
            for (int mf = 0; mf < 4; mf++) {
                int rowL = m0 + mf * 16 + laneA;
                int cu = 2 * ks + cA;
                ldsm4(Af[mf], sA + (uint32_t)(rowL << 7) + (uint32_t)((cu ^ (rowL & 7)) << 4));
            }
#pragma unroll
            for (int g4 = 0; g4 < 4; g4++) {
                int cu = 2 * ks + cB;
                uint32_t t[4];
                ldsm4(t, bBase[g4] + ((cu ^ bS7[g4]) << 4));
                Bf[2 * g4][0] = t[0]; Bf[2 * g4][1] = t[1];
                Bf[2 * g4 + 1][0] = t[2]; Bf[2 * g4 + 1][1] = t[3];
            }
#pragma unroll
            for (int mf = 0; mf < 4; mf++)
#pragma unroll
                for (int nf = 0; nf < 8; nf++) mma16816(acc[mf][nf], Af[mf], Bf[nf]);
        }
    }

    if (a.mode == 0) {
        // plain matrix write: CW[m][n] = acc + bias
#pragma unroll
        for (int mf = 0; mf < 4; mf++) {
            int rl = m0 + mf * 16 + (lane >> 2);
            int m = mt * 128 + rl;
            float bv0 = a.bias[m & 3][m >> 2];
            float bv1 = a.bias[(m + 8) & 3][(m + 8) >> 2];
#pragma unroll
            for (int nf = 0; nf < 8; nf++) {
                int n = nt * 256 + n0 + nf * 8 + ((lane & 3) << 1);
                *(float2*)(a.cw + (size_t)m * 2048 + n) =
                    make_float2(acc[mf][nf][0] + bv0, acc[mf][nf][1] + bv0);
                *(float2*)(a.cw + (size_t)(m + 8) * 2048 + n) =
                    make_float2(acc[mf][nf][2] + bv1, acc[mf][nf][3] + bv1);
            }
        }
    } else {
        // fused LSTM epilogue
        __syncthreads();                 // all warps done with pipeline smem
        float* S = (float*)sm;           // [128][SPITCH]
#pragma unroll
        for (int mf = 0; mf < 4; mf++) {
            int rl = m0 + mf * 16 + (lane >> 2);
            int m = mt * 128 + rl;
            float bv0 = a.bias[m & 3][m >> 2];
            float bv1 = a.bias[(m + 8) & 3][(m + 8) >> 2];
#pragma unroll
            for (int nf = 0; nf < 8; nf++) {
                int hw = n0 + nf * 8 + ((lane & 3) << 1);
                int n = nt * 256 + hw;
                float2 b0 = *(const float2*)(a.cw + (size_t)m * 2048 + n);
                float2 b1 = *(const float2*)(a.cw + (size_t)(m + 8) * 2048 + n);
                S[rl * SPITCH + hw]           = acc[mf][nf][0] + bv0 + b0.x;
                S[rl * SPITCH + hw + 1]       = acc[mf][nf][1] + bv0 + b0.y;
                S[(rl + 8) * SPITCH + hw]     = acc[mf][nf][2] + bv1 + b1.x;
                S[(rl + 8) * SPITCH + hw + 1] = acc[mf][nf][3] + bv1 + b1.y;
            }
        }
        __syncthreads();
        __half* smXt = (__half*)(sm + SMXT_OFF);   // [256 hw][32 cout]
        int jq = tid >> 3;               // local cout 0..31
        int hw0 = (tid & 7) * 32;
        int cout = mt * 32 + jq;
        size_t cbase = ((size_t)nt * 512 + cout) * 256;
#pragma unroll 2
        for (int u = 0; u < 32; u += 4) {
            int hw = hw0 + u;
            float4 cp = *(const float4*)(a.cprev + cbase + hw);
            float cv[4], hv[4];
#pragma unroll
            for (int e = 0; e < 4; e++) {
                float gi = S[(4 * jq + 0) * SPITCH + hw + e];
                float gf = S[(4 * jq + 1) * SPITCH + hw + e];
                float gc = S[(4 * jq + 2) * SPITCH + hw + e];
                float go = S[(4 * jq + 3) * SPITCH + hw + e];
                float ii = 1.f / (1.f + expf(-gi));
                float ff = 1.f / (1.f + expf(-gf));
                float gg = tanhf(gc);
                float oo = 1.f / (1.f + expf(-go));
                float cc = gg * ii + ff * (&cp.x)[e];
                cv[e] = cc;
                hv[e] = tanhf(cc) * oo;
            }
            *(float4*)(a.cnew + cbase + hw) = make_float4(cv[0], cv[1], cv[2], cv[3]);
            if (a.mode == 2) {
                *(float4*)(a.out + cbase + hw) = make_float4(hv[0], hv[1], hv[2], hv[3]);
            } else {
#pragma unroll
                for (int e = 0; e < 4; e++)
                    smXt[(hw + e) * 32 + jq] = __float2half_rn(hv[e]);
            }
        }
        if (a.mode == 1) {
            __syncthreads();
            // thread tid = hw row: write 32 couts (64B) to Xt
            uint4* src = (uint4*)(smXt + tid * 32);
            uint4* dst = (uint4*)(g_Xt + ((size_t)(nt * 256 + tid)) * 512 + mt * 32);
            dst[0] = src[0]; dst[1] = src[1]; dst[2] = src[2]; dst[3] = src[3];
        }
    }
}

// ---------------- launch ----------------
extern "C" void kernel_launch(void* const* d_in, const int* in_sizes, int n_in,
                              void* d_out, int out_size) {
    const float* x    = (const float*)d_in[0];
    const float* txt  = (const float*)d_in[1];
    // d_in[2..6] dead (softmax over size-1 axis == 1)
    const float* Wi_w = (const float*)d_in[7];
    const float* Wi_b = (const float*)d_in[8];
    const float* Ui_w = (const float*)d_in[9];
    const float* Ui_b = (const float*)d_in[10];
    const float* Wf_w = (const float*)d_in[11];
    const float* Wf_b = (const float*)d_in[12];
    const float* Uf_w = (const float*)d_in[13];
    const float* Uf_b = (const float*)d_in[14];
    const float* Wc_w = (const float*)d_in[15];
    const float* Wc_b = (const float*)d_in[16];
    const float* Uc_w = (const float*)d_in[17];
    const float* Uc_b = (const float*)d_in[18];
    const float* Wo_w = (const float*)d_in[19];
    const float* Wo_b = (const float*)d_in[20];
    const float* Uo_w = (const float*)d_in[21];
    const float* Uo_b = (const float*)d_in[22];
    const float* WQ   = (const float*)d_in[23];
    const float* WK   = (const float*)d_in[24];
    const float* WV   = (const float*)d_in[25];
    const float* Wsw  = (const float*)d_in[26];
    const float* Wsb  = (const float*)d_in[27];
    float* out = (float*)d_out;

    float *pCW, *pC;
    __half *pWh;
    cudaGetSymbolAddress((void**)&pCW, g_CW);
    cudaGetSymbolAddress((void**)&pC,  g_c);
    cudaGetSymbolAddress((void**)&pWh, g_Wh);

    cudaFuncSetAttribute(k_gemm, cudaFuncAttributeMaxDynamicSharedMemorySize, GEMM_SMEM);

    WPtrs wp;
    wp.p[0] = Wi_w; wp.p[1] = Wf_w; wp.p[2] = Wc_w; wp.p[3] = Wo_w;
    wp.p[4] = Ui_w; wp.p[5] = Uf_w; wp.p[6] = Uc_w; wp.p[7] = Uo_w;
    k_wsplit<<<4096, 256>>>(wp);

    k_m<<<256, 256>>>(WQ, WK);
    k_att<<<8, 256>>>(txt, WV, Wsw, Wsb);

    // CW = conv(AM, W) + bias (AM = myA*x applied inside prep)
    k_prep<<<dim3(4, 8, 8), 256>>>(x, 1);
    {
        GArgs ga;
        ga.Aw = pWh;
        ga.bias[0] = Wi_b; ga.bias[1] = Wf_b; ga.bias[2] = Wc_b; ga.bias[3] = Wo_b;
        ga.cw = pCW; ga.cprev = nullptr; ga.cnew = nullptr; ga.out = nullptr;
        ga.mode = 0;
        k_gemm<<<dim3(16, 8), 256, GEMM_SMEM>>>(ga);
    }

    // recurrence: conv(h, U) + CW, fused LSTM update in epilogue
    k_prep<<<dim3(4, 8, 8), 256>>>(x, 0);
    for (int ts = 0; ts < 4; ts++) {
        GArgs gu;
        gu.Aw = pWh + (size_t)MROWS * KDIM;
        gu.bias[0] = Ui_b; gu.bias[1] = Uf_b; gu.bias[2] = Uc_b; gu.bias[3] = Uo_b;
        gu.cw = pCW;
        gu.cprev = (ts == 0) ? x : pC;
        gu.cnew = pC;
        gu.out = out;
        gu.mode = (ts == 3) ? 2 : 1;
        k_gemm<<<dim3(16, 8), 256, GEMM_SMEM>>>(gu);
    }
}